// round 14
// baseline (speedup 1.0000x reference)
#include <cuda_runtime.h>
#include <cuda_fp16.h>
#include <cstdint>
#include <cstddef>

#define C   128
#define N0  20000
#define E1V 500000
#define E2V 500000
#define TV  500000

// ---------------- static device scratch (no allocations allowed) ----------------
__device__ __half g_y0h[(size_t)N0 * C];
__device__ __half g_y1h[(size_t)E1V * C];
__device__ __half g_y2h[(size_t)E2V * C];
__device__ float  g_a0[(size_t)N0 * C];     // RED accumulators, zeroed by consumers
__device__ float  g_a1[(size_t)E1V * C];
__device__ float  g_a2[(size_t)E2V * C];
__device__ __half g_v[(size_t)E1V * C];     // part-b linear output (f16, RED target)

__device__ __forceinline__ void red2(float* p, float a, float b) {
    asm volatile("red.global.add.v2.f32 [%0], {%1,%2};"
                 :: "l"(p), "f"(a), "f"(b) : "memory");
}
__device__ __forceinline__ void redh1(__half* p, uint32_t v) {
    asm volatile("red.global.add.noftz.f16x2 [%0], %1;"
                 :: "l"(p), "r"(v) : "memory");
}
// pack two f32 -> f16x2
__device__ __forceinline__ uint32_t pk(float lo, float hi) {
    uint32_t d;
    asm("cvt.rn.f16x2.f32 %0, %1, %2;" : "=r"(d) : "f"(hi), "f"(lo));
    return d;
}
// two f16x2 words -> float4
__device__ __forceinline__ float4 two_words(uint32_t w0, uint32_t w1) {
    float2 a = __half22float2(*(__half2*)&w0);
    float2 b = __half22float2(*(__half2*)&w1);
    return make_float4(a.x, a.y, b.x, b.y);
}
// relu(ha + hb + bias) packed
__device__ __forceinline__ uint32_t gath_word(uint32_t ua, uint32_t ub, float2 bi) {
    float2 fa = __half22float2(*(__half2*)&ua);
    float2 fb = __half22float2(*(__half2*)&ub);
    return pk(fmaxf(fa.x + fb.x + bi.x, 0.f), fmaxf(fa.y + fb.y + bi.y, 0.f));
}

// ---- f16 tile layout: 128 rows, 8 k16-groups of 8 f16x2 words, row stride 72 ----
#define ROWW 72
#define TWORDS (128 * ROWW)
__device__ __forceinline__ int widx(int r, int g, int p) { return r * ROWW + g * 8 + p; }

// permute linear words [0..7] -> [0,4,1,5,2,6,3,7] per 8-word half
__device__ __forceinline__ void permute16(const uint32_t* lin, uint32_t* w) {
#pragma unroll
    for (int h = 0; h < 2; h++) {
        const uint32_t* i8 = lin + h * 8;
        uint32_t* o = w + h * 8;
        o[0] = i8[0]; o[1] = i8[4]; o[2] = i8[1]; o[3] = i8[5];
        o[4] = i8[2]; o[5] = i8[6]; o[6] = i8[3]; o[7] = i8[7];
    }
}

// LDG a 128x128 fp32 tile -> 16 packed f16x2 regs.
__device__ __forceinline__ void ldg_tile(const float* A, int row0, int M,
                                         int tid, uint32_t* w)
{
    const int row = row0 + (tid >> 2), q = tid & 3;
    uint32_t lin[16];
#pragma unroll
    for (int j = 0; j < 16; j++) lin[j] = 0;
    if (row < M) {
        const float4* g = (const float4*)(A + (size_t)row * C + q * 32);
#pragma unroll
        for (int j = 0; j < 8; j++) {
            float4 f = g[j];
            lin[j * 2 + 0] = pk(f.x, f.y);
            lin[j * 2 + 1] = pk(f.z, f.w);
        }
    }
    permute16(lin, w);
}

// Gathered A tile: row r = relu(ya[iA[r]] + yb[iB[r]] + binner), f16 sources.
__device__ __forceinline__ void ldg_gather(const __half* ya, const __half* yb,
                                           const int* iA, const int* iB,
                                           const float* binner, int row0, int M,
                                           int tid, uint32_t* w)
{
    const int r = row0 + (tid >> 2), q = tid & 3;
    uint32_t lin[16];
    if (r < M) {
        const int a = iA[r], b = iB[r];
        const uint4* ga = (const uint4*)(ya + (size_t)a * C + q * 32);
        const uint4* gb = (const uint4*)(yb + (size_t)b * C + q * 32);
        uint4 va[4], vb[4];
#pragma unroll
        for (int j = 0; j < 4; j++) { va[j] = ga[j]; vb[j] = gb[j]; }
        const float* bi = binner + q * 32;
#pragma unroll
        for (int j = 0; j < 4; j++) {
            float2 b0 = *(const float2*)(bi + j * 8 + 0);
            float2 b1 = *(const float2*)(bi + j * 8 + 2);
            float2 b2 = *(const float2*)(bi + j * 8 + 4);
            float2 b3 = *(const float2*)(bi + j * 8 + 6);
            lin[j * 4 + 0] = gath_word(va[j].x, vb[j].x, b0);
            lin[j * 4 + 1] = gath_word(va[j].y, vb[j].y, b1);
            lin[j * 4 + 2] = gath_word(va[j].z, vb[j].z, b2);
            lin[j * 4 + 3] = gath_word(va[j].w, vb[j].w, b3);
        }
    } else {
#pragma unroll
        for (int j = 0; j < 16; j++) lin[j] = 0;
    }
    permute16(lin, w);
}

__device__ __forceinline__ void sts_tile(uint32_t* buf, int tid, const uint32_t* w)
{
    const int row = tid >> 2, q = tid & 3;
    *(uint4*)(buf + widx(row, 2 * q,     0)) = make_uint4(w[0],  w[1],  w[2],  w[3]);
    *(uint4*)(buf + widx(row, 2 * q,     4)) = make_uint4(w[4],  w[5],  w[6],  w[7]);
    *(uint4*)(buf + widx(row, 2 * q + 1, 0)) = make_uint4(w[8],  w[9],  w[10], w[11]);
    *(uint4*)(buf + widx(row, 2 * q + 1, 4)) = make_uint4(w[12], w[13], w[14], w[15]);
}

__device__ __forceinline__ void mma_f16(const uint32_t* Ab, const uint32_t* Wb,
                                        int wm, int wn, int gid, int tig,
                                        float acc[2][4][4])
{
#pragma unroll
    for (int g = 0; g < 8; g++) {
        uint32_t af[2][4], bf[4][2];
#pragma unroll
        for (int t = 0; t < 2; t++) {
            const int rl = wm + t * 16 + gid;
            uint2 lo = *(const uint2*)(Ab + widx(rl,     g, tig * 2));
            uint2 hi = *(const uint2*)(Ab + widx(rl + 8, g, tig * 2));
            af[t][0] = lo.x; af[t][1] = hi.x; af[t][2] = lo.y; af[t][3] = hi.y;
        }
#pragma unroll
        for (int tb = 0; tb < 4; tb++) {
            const int n = wn + tb * 8 + gid;
            uint2 b = *(const uint2*)(Wb + widx(n, g, tig * 2));
            bf[tb][0] = b.x; bf[tb][1] = b.y;
        }
#pragma unroll
        for (int t = 0; t < 2; t++)
#pragma unroll
            for (int tb = 0; tb < 4; tb++)
                asm("mma.sync.aligned.m16n8k16.row.col.f32.f16.f16.f32 "
                    "{%0,%1,%2,%3}, {%4,%5,%6,%7}, {%8,%9}, {%0,%1,%2,%3};"
                    : "+f"(acc[t][tb][0]), "+f"(acc[t][tb][1]),
                      "+f"(acc[t][tb][2]), "+f"(acc[t][tb][3])
                    : "r"(af[t][0]), "r"(af[t][1]), "r"(af[t][2]), "r"(af[t][3]),
                      "r"(bf[tb][0]), "r"(bf[tb][1]));
    }
}

#define GEMM_SMEM (3 * TWORDS * 4)

// ===== projection GEMM: y(half) = A(f32) @ W^T ; optional fused node-scatter =====
// SCAT: a0scat[sidx[r]] += relu(y[r] + bscat)  (a0 is L2-resident, red2 fp32)
template<bool SCAT>
__global__ __launch_bounds__(512, 1)
void tgemm(const float* __restrict__ A, const float* __restrict__ W,
           __half* __restrict__ Cout, const int* __restrict__ sidx,
           const float* __restrict__ bscat, float* __restrict__ a0scat,
           int M, int ntiles)
{
    extern __shared__ uint32_t sm[];
    uint32_t* Wf = sm;
    uint32_t* Ab[2] = { sm + TWORDS, sm + 2 * TWORDS };
    const int tid = threadIdx.x;
    const int lane = tid & 31, warp = tid >> 5;
    const int gid = lane >> 2, tig = lane & 3;
    const int wm = (warp >> 2) * 32, wn = (warp & 3) * 32;

    uint32_t w[16];
    int tile = blockIdx.x;
    { uint32_t ww[16]; ldg_tile(W, 0, 128, tid, ww); sts_tile(Wf, tid, ww); }
    if (tile < ntiles) { ldg_tile(A, tile * 128, M, tid, w); sts_tile(Ab[0], tid, w); }
    __syncthreads();

    int buf = 0;
    for (; tile < ntiles; tile += gridDim.x) {
        const int nxt = tile + gridDim.x;
        const bool hn = nxt < ntiles;
        if (hn) ldg_tile(A, nxt * 128, M, tid, w);

        float acc[2][4][4];
#pragma unroll
        for (int t = 0; t < 2; t++)
#pragma unroll
            for (int tb = 0; tb < 4; tb++)
#pragma unroll
                for (int i = 0; i < 4; i++) acc[t][tb][i] = 0.f;
        mma_f16(Ab[buf], Wf, wm, wn, gid, tig, acc);

        if (hn) sts_tile(Ab[buf ^ 1], tid, w);
#pragma unroll
        for (int t = 0; t < 2; t++) {
            const int r = tile * 128 + wm + t * 16 + gid;
            int d0 = 0, d1 = 0;
            if (SCAT) {
                if (r < M)     d0 = sidx[r];
                if (r + 8 < M) d1 = sidx[r + 8];
            }
#pragma unroll
            for (int tb = 0; tb < 4; tb++) {
                const int cc = wn + tb * 8 + tig * 2;
                float2 bs;
                if (SCAT) bs = *(const float2*)(bscat + cc);
                if (r < M) {
                    *(uint32_t*)(Cout + (size_t)r * C + cc) =
                        pk(acc[t][tb][0], acc[t][tb][1]);
                    if (SCAT)
                        red2(a0scat + (size_t)d0 * C + cc,
                             fmaxf(acc[t][tb][0] + bs.x, 0.f),
                             fmaxf(acc[t][tb][1] + bs.y, 0.f));
                }
                if (r + 8 < M) {
                    *(uint32_t*)(Cout + (size_t)(r + 8) * C + cc) =
                        pk(acc[t][tb][2], acc[t][tb][3]);
                    if (SCAT)
                        red2(a0scat + (size_t)d1 * C + cc,
                             fmaxf(acc[t][tb][2] + bs.x, 0.f),
                             fmaxf(acc[t][tb][3] + bs.y, 0.f));
                }
            }
        }
        __syncthreads();
        buf ^= 1;
    }
}

// ============ gather-GEMM-scatter: dst[iD[r]] += relu(ya[iA]+yb[iB]+bi) @ W^T ====
template<bool OUTH>
__global__ __launch_bounds__(512, 1)
void ggemm(const __half* __restrict__ ya, const __half* __restrict__ yb,
           const int* __restrict__ iA, const int* __restrict__ iB,
           const int* __restrict__ iD, const float* __restrict__ binner,
           const float* __restrict__ W, void* __restrict__ dst, int M, int ntiles)
{
    extern __shared__ uint32_t sm[];
    uint32_t* Wf = sm;
    uint32_t* Ab[2] = { sm + TWORDS, sm + 2 * TWORDS };
    const int tid = threadIdx.x;
    const int lane = tid & 31, warp = tid >> 5;
    const int gid = lane >> 2, tig = lane & 3;
    const int wm = (warp >> 2) * 32, wn = (warp & 3) * 32;

    uint32_t w[16];
    int tile = blockIdx.x;
    { uint32_t ww[16]; ldg_tile(W, 0, 128, tid, ww); sts_tile(Wf, tid, ww); }
    if (tile < ntiles) {
        ldg_gather(ya, yb, iA, iB, binner, tile * 128, M, tid, w);
        sts_tile(Ab[0], tid, w);
    }
    __syncthreads();

    int buf = 0;
    for (; tile < ntiles; tile += gridDim.x) {
        const int nxt = tile + gridDim.x;
        const bool hn = nxt < ntiles;
        if (hn) ldg_gather(ya, yb, iA, iB, binner, nxt * 128, M, tid, w);

        float acc[2][4][4];
#pragma unroll
        for (int t = 0; t < 2; t++)
#pragma unroll
            for (int tb = 0; tb < 4; tb++)
#pragma unroll
                for (int i = 0; i < 4; i++) acc[t][tb][i] = 0.f;
        mma_f16(Ab[buf], Wf, wm, wn, gid, tig, acc);

        if (hn) sts_tile(Ab[buf ^ 1], tid, w);

#pragma unroll
        for (int t = 0; t < 2; t++) {
            const int r = tile * 128 + wm + t * 16 + gid;
            if (r < M) {
                const size_t base = (size_t)iD[r] * C;
#pragma unroll
                for (int tb = 0; tb < 4; tb++) {
                    const int cc = wn + tb * 8 + tig * 2;
                    if (OUTH)
                        redh1((__half*)dst + base + cc, pk(acc[t][tb][0], acc[t][tb][1]));
                    else
                        red2((float*)dst + base + cc, acc[t][tb][0], acc[t][tb][1]);
                }
            }
            if (r + 8 < M) {
                const size_t base = (size_t)iD[r + 8] * C;
#pragma unroll
                for (int tb = 0; tb < 4; tb++) {
                    const int cc = wn + tb * 8 + tig * 2;
                    if (OUTH)
                        redh1((__half*)dst + base + cc, pk(acc[t][tb][2], acc[t][tb][3]));
                    else
                        red2((float*)dst + base + cc, acc[t][tb][2], acc[t][tb][3]);
                }
            }
        }
        __syncthreads();
        buf ^= 1;
    }
}

// ======================= fused 2-layer MLP (f16) =================================
// MLP input per row r:
//   Aa[r] (fp32 RED accumulator; zeroed after read)
// + X[r]
// + (WITHE) relu(y0[se[r]] + y0[se[r+M]] + bi) + cb1 + cb2
// + (WITHV) v[r] + v[inv1[r]]
// out = relu(in@Wa^T + ba) @ Wb^T + bb + X
// zp: zero zp rows while streaming (restores v for the next replay)
#define FMLP_SMEM (4 * TWORDS * 4)
template<bool WITHE, bool WITHV>
__global__ __launch_bounds__(512, 1)
void fmlp(float* __restrict__ Aa, const float* __restrict__ X,
          const float* __restrict__ Wa, const float* __restrict__ ba,
          const float* __restrict__ Wb, const float* __restrict__ bb,
          float* __restrict__ out,
          const __half* __restrict__ y0, const int* __restrict__ se,
          const float* __restrict__ bi, const float* __restrict__ cb1,
          const float* __restrict__ cb2,
          const __half* __restrict__ v, const int* __restrict__ inv1,
          __half* __restrict__ zp, int M, int ntiles)
{
    extern __shared__ uint32_t sm[];
    uint32_t* Wfa = sm;
    uint32_t* Wfb = sm + TWORDS;
    uint32_t* Ab[2] = { sm + 2 * TWORDS, sm + 3 * TWORDS };
    const int tid = threadIdx.x;
    const int lane = tid & 31, warp = tid >> 5;
    const int gid = lane >> 2, tig = lane & 3;
    const int wm = (warp >> 2) * 32, wn = (warp & 3) * 32;
    const int lrow = tid >> 2, q = tid & 3;

    auto ld = [&](int row0, uint32_t* dst) {
        const int r = row0 + lrow;
        uint32_t lin[16];
#pragma unroll
        for (int j = 0; j < 16; j++) lin[j] = 0;
        if (r < M) {
            float4 f[8];
            const float4* ga = (const float4*)(Aa + (size_t)r * C + q * 32);
            const float4* gx = (const float4*)(X + (size_t)r * C + q * 32);
#pragma unroll
            for (int j = 0; j < 8; j++) {
                float4 av = ga[j], xv = gx[j];
                f[j].x = av.x + xv.x; f[j].y = av.y + xv.y;
                f[j].z = av.z + xv.z; f[j].w = av.w + xv.w;
            }
            if (WITHE) {
                const int s = se[r], e = se[r + M];
                const uint4* gs = (const uint4*)(y0 + (size_t)s * C + q * 32);
                const uint4* ge = (const uint4*)(y0 + (size_t)e * C + q * 32);
                const float* bip = bi + q * 32;
                const float* c1p = cb1 + q * 32;
                const float* c2p = cb2 + q * 32;
#pragma unroll
                for (int j = 0; j < 4; j++) {
                    uint4 us = gs[j], ue = ge[j];
                    float4 s0 = two_words(us.x, us.y), s1 = two_words(us.z, us.w);
                    float4 e0 = two_words(ue.x, ue.y), e1 = two_words(ue.z, ue.w);
                    float4 b0 = *(const float4*)(bip + j * 8);
                    float4 b1 = *(const float4*)(bip + j * 8 + 4);
                    float4 c0a = *(const float4*)(c1p + j * 8);
                    float4 c1a = *(const float4*)(c1p + j * 8 + 4);
                    float4 c0b = *(const float4*)(c2p + j * 8);
                    float4 c1b = *(const float4*)(c2p + j * 8 + 4);
                    f[2 * j].x += fmaxf(s0.x + e0.x + b0.x, 0.f) + c0a.x + c0b.x;
                    f[2 * j].y += fmaxf(s0.y + e0.y + b0.y, 0.f) + c0a.y + c0b.y;
                    f[2 * j].z += fmaxf(s0.z + e0.z + b0.z, 0.f) + c0a.z + c0b.z;
                    f[2 * j].w += fmaxf(s0.w + e0.w + b0.w, 0.f) + c0a.w + c0b.w;
                    f[2 * j + 1].x += fmaxf(s1.x + e1.x + b1.x, 0.f) + c1a.x + c1b.x;
                    f[2 * j + 1].y += fmaxf(s1.y + e1.y + b1.y, 0.f) + c1a.y + c1b.y;
                    f[2 * j + 1].z += fmaxf(s1.z + e1.z + b1.z, 0.f) + c1a.z + c1b.z;
                    f[2 * j + 1].w += fmaxf(s1.w + e1.w + b1.w, 0.f) + c1a.w + c1b.w;
                }
            }
            if (WITHV) {
                const int gi = inv1[r];
                const uint4* gv = (const uint4*)(v + (size_t)r * C + q * 32);
                const uint4* gg = (const uint4*)(v + (size_t)gi * C + q * 32);
#pragma unroll
                for (int j = 0; j < 4; j++) {
                    uint4 av = gv[j], ag = gg[j];
                    float4 s0 = two_words(av.x, av.y), s1 = two_words(av.z, av.w);
                    float4 t0 = two_words(ag.x, ag.y), t1 = two_words(ag.z, ag.w);
                    f[2 * j].x     += s0.x + t0.x; f[2 * j].y     += s0.y + t0.y;
                    f[2 * j].z     += s0.z + t0.z; f[2 * j].w     += s0.w + t0.w;
                    f[2 * j + 1].x += s1.x + t1.x; f[2 * j + 1].y += s1.y + t1.y;
                    f[2 * j + 1].z += s1.z + t1.z; f[2 * j + 1].w += s1.w + t1.w;
                }
            }
#pragma unroll
            for (int j = 0; j < 8; j++) {
                lin[j * 2 + 0] = pk(f[j].x, f[j].y);
                lin[j * 2 + 1] = pk(f[j].z, f[j].w);
            }
            // zero the a-buffer row for the next replay
            {
                float4* za = (float4*)(Aa + (size_t)r * C + q * 32);
#pragma unroll
                for (int j = 0; j < 8; j++) za[j] = make_float4(0.f, 0.f, 0.f, 0.f);
            }
            if (zp) {
                uint4* z = (uint4*)(zp + (size_t)r * C + q * 32);
#pragma unroll
                for (int j = 0; j < 4; j++) z[j] = make_uint4(0, 0, 0, 0);
            }
        }
        permute16(lin, dst);
    };

    uint32_t w[16];
    int tile = blockIdx.x;
    { uint32_t ww[16]; ldg_tile(Wa, 0, 128, tid, ww); sts_tile(Wfa, tid, ww); }
    { uint32_t ww[16]; ldg_tile(Wb, 0, 128, tid, ww); sts_tile(Wfb, tid, ww); }
    if (tile < ntiles) { ld(tile * 128, w); sts_tile(Ab[0], tid, w); }
    __syncthreads();

    int buf = 0;
    for (; tile < ntiles; tile += gridDim.x) {
        const int nxt = tile + gridDim.x;
        const bool hn = nxt < ntiles;
        if (hn) ld(nxt * 128, w);

        float acc[2][4][4];
#pragma unroll
        for (int t = 0; t < 2; t++)
#pragma unroll
            for (int tb = 0; tb < 4; tb++)
#pragma unroll
                for (int i = 0; i < 4; i++) acc[t][tb][i] = 0.f;
        mma_f16(Ab[buf], Wfa, wm, wn, gid, tig, acc);
        __syncthreads();

        {   // hidden = relu(acc + ba) -> back into Ab[buf]
            const int gbase = wn >> 4;
#pragma unroll
            for (int t = 0; t < 2; t++) {
                const int rl = wm + t * 16 + gid;
#pragma unroll
                for (int tb = 0; tb < 4; tb++) {
                    const int cc = wn + tb * 8 + tig * 2;
                    const int g = gbase + (tb >> 1);
                    const int p = 2 * tig + (tb & 1);
                    float2 b2 = *(const float2*)(ba + cc);
                    Ab[buf][widx(rl,     g, p)] = pk(fmaxf(acc[t][tb][0] + b2.x, 0.f),
                                                     fmaxf(acc[t][tb][1] + b2.y, 0.f));
                    Ab[buf][widx(rl + 8, g, p)] = pk(fmaxf(acc[t][tb][2] + b2.x, 0.f),
                                                     fmaxf(acc[t][tb][3] + b2.y, 0.f));
                }
            }
        }
        __syncthreads();

#pragma unroll
        for (int t = 0; t < 2; t++)
#pragma unroll
            for (int tb = 0; tb < 4; tb++)
#pragma unroll
                for (int i = 0; i < 4; i++) acc[t][tb][i] = 0.f;
        mma_f16(Ab[buf], Wfb, wm, wn, gid, tig, acc);

        if (hn) sts_tile(Ab[buf ^ 1], tid, w);
#pragma unroll
        for (int t = 0; t < 2; t++) {
            const int r = tile * 128 + wm + t * 16 + gid;
#pragma unroll
            for (int tb = 0; tb < 4; tb++) {
                const int cc = wn + tb * 8 + tig * 2;
                float2 bb2 = *(const float2*)(bb + cc);
                if (r < M) {
                    float2 o = *(const float2*)(X + (size_t)r * C + cc);
                    *(float2*)(out + (size_t)r * C + cc) =
                        make_float2(acc[t][tb][0] + bb2.x + o.x,
                                    acc[t][tb][1] + bb2.y + o.y);
                }
                if (r + 8 < M) {
                    float2 o = *(const float2*)(X + (size_t)(r + 8) * C + cc);
                    *(float2*)(out + (size_t)(r + 8) * C + cc) =
                        make_float2(acc[t][tb][2] + bb2.x + o.x,
                                    acc[t][tb][3] + bb2.y + o.y);
                }
            }
        }
        __syncthreads();
        buf ^= 1;
    }
}

// ================================================================================
template<bool SCAT>
static inline void run_tgemm(const float* A, const float* W, __half* Co,
                             const int* sidx, const float* bscat, float* a0, int M)
{
    int nt = (M + 127) / 128;
    int grid = nt < 148 ? nt : 148;
    cudaFuncSetAttribute(tgemm<SCAT>, cudaFuncAttributeMaxDynamicSharedMemorySize, GEMM_SMEM);
    tgemm<SCAT><<<grid, 512, GEMM_SMEM>>>(A, W, Co, sidx, bscat, a0, M, nt);
}

template<bool OUTH>
static inline void run_ggemm(const __half* ya, const __half* yb, const int* iA,
                             const int* iB, const int* iD, const float* bi,
                             const float* W, void* dst, int M)
{
    int nt = (M + 127) / 128;
    int grid = nt < 148 ? nt : 148;
    cudaFuncSetAttribute(ggemm<OUTH>, cudaFuncAttributeMaxDynamicSharedMemorySize, GEMM_SMEM);
    ggemm<OUTH><<<grid, 512, GEMM_SMEM>>>(ya, yb, iA, iB, iD, bi, W, dst, M, nt);
}

template<bool WITHE, bool WITHV>
static inline void run_fmlp(float* Aa, const float* X, const float* Wa,
                            const float* ba, const float* Wb, const float* bb,
                            float* out, const __half* y0, const int* se,
                            const float* bi, const float* cb1, const float* cb2,
                            const __half* v, const int* inv1, __half* zp, int M)
{
    int nt = (M + 127) / 128;
    int grid = nt < 148 ? nt : 148;
    cudaFuncSetAttribute(fmlp<WITHE, WITHV>,
                         cudaFuncAttributeMaxDynamicSharedMemorySize, FMLP_SMEM);
    fmlp<WITHE, WITHV><<<grid, 512, FMLP_SMEM>>>(Aa, X, Wa, ba, Wb, bb, out,
                                                 y0, se, bi, cb1, cb2,
                                                 v, inv1, zp, M, nt);
}

extern "C" void kernel_launch(void* const* d_in, const int* in_sizes, int n_in,
                              void* d_out, int out_size)
{
    (void)in_sizes; (void)n_in; (void)out_size;
    const float* x0   = (const float*)d_in[0];
    const float* x1   = (const float*)d_in[1];
    const float* x2   = (const float*)d_in[2];
    const int*   ei1  = (const int*)d_in[3];
    const int*   ei2  = (const int*)d_in[4];
    const int*   t111 = (const int*)d_in[5];
    const int*   t222 = (const int*)d_in[6];
    const int*   t112 = (const int*)d_in[7];
    const int*   inv1 = (const int*)d_in[8];
    const float* WiW  = (const float*)d_in[10]; const float* Wib  = (const float*)d_in[11];
    const float* l111W= (const float*)d_in[12]; const float* l111b= (const float*)d_in[13];
    const float* l222W= (const float*)d_in[14]; const float* l222b= (const float*)d_in[15];
    const float* l211W= (const float*)d_in[16]; const float* l211b= (const float*)d_in[17];
    const float* m0aW = (const float*)d_in[18]; const float* m0ab = (const float*)d_in[19];
    const float* m0bW = (const float*)d_in[20]; const float* m0bb = (const float*)d_in[21];
    const float* m1aW = (const float*)d_in[22]; const float* m1ab = (const float*)d_in[23];
    const float* m1bW = (const float*)d_in[24]; const float* m1bb = (const float*)d_in[25];
    const float* m2aW = (const float*)d_in[26]; const float* m2ab = (const float*)d_in[27];
    const float* m2bW = (const float*)d_in[28]; const float* m2bb = (const float*)d_in[29];
    float* out = (float*)d_out;

    __half *y0, *y1, *y2, *v;
    float *a0, *a1, *a2;
    cudaGetSymbolAddress((void**)&y0, g_y0h);
    cudaGetSymbolAddress((void**)&y1, g_y1h);
    cudaGetSymbolAddress((void**)&y2, g_y2h);
    cudaGetSymbolAddress((void**)&a0, g_a0);
    cudaGetSymbolAddress((void**)&a1, g_a1);
    cudaGetSymbolAddress((void**)&a2, g_a2);
    cudaGetSymbolAddress((void**)&v,  g_v);

    // a0/a1/a2/v are zero at the start of every replay: device globals are
    // zero-initialized, and each consumer below re-zeroes its buffer inline.

    // projections; x1/x2 projections fuse the node scatter into a0 (L2-resident)
    run_tgemm<false>(x0, WiW, y0, nullptr, nullptr, nullptr, N0);           // 1
    run_tgemm<true >(x1, WiW, y1, ei1, Wib, a0, E1V);                       // 2
    run_tgemm<true >(x2, WiW, y2, ei2, Wib, a0, E2V);                       // 3

    // fused gather-GEMM-scatter aggregation passes (a1/a2 are pure RED targets)
    // (1,1,1): a1[t0] += L111(relu(y1[t1]+y1[t2]+b))                       // 4
    run_ggemm<false>(y1, y1, t111 + TV, t111 + 2 * TV, t111, Wib, l111W, a1, TV);
    // (2,2,2): a2[t0] += L222(relu(y2[t1]+y2[t2]+b))                       // 5
    run_ggemm<false>(y2, y2, t222 + TV, t222 + 2 * TV, t222, Wib, l222W, a2, TV);
    // (1,1,2) part a: a2[t2] += L211(relu(y1[t0]+y1[t1]+b))   <- ncu slot 6
    run_ggemm<false>(y1, y1, t112, t112 + TV, t112 + 2 * TV, Wib, l211W, a2, TV);
    // (1,1,2) part b: v[t0] += L211(relu(y1[t1]+y2[t2]+b))   (f16 RED)     // 7
    run_ggemm<true>(y1, y2, t112 + TV, t112 + 2 * TV, t112, Wib, l211W, v, TV);

    // fused output MLPs: loader assembles x + edge-term + REDs (+v terms),
    // zeroes the a-buffer (and fmlp2 zeroes v) for the next replay.
    run_fmlp<false, false>(a0, x0, m0aW, m0ab, m0bW, m0bb, out,
                           nullptr, nullptr, nullptr, nullptr, nullptr,
                           nullptr, nullptr, nullptr, N0);                  // 8
    run_fmlp<true, true>(a1, x1, m1aW, m1ab, m1bW, m1bb, out + (size_t)N0 * C,
                         y0, ei1, Wib, l111b, l211b, v, inv1, nullptr, E1V); // 9
    run_fmlp<true, false>(a2, x2, m2aW, m2ab, m2bW, m2bb,
                          out + ((size_t)N0 + E1V) * C,
                          y0, ei2, Wib, l222b, l211b, nullptr, nullptr, v, E2V); // 10
}

// round 15
// speedup vs baseline: 1.1934x; 1.1934x over previous
#include <cuda_runtime.h>
#include <cuda_fp16.h>
#include <cstdint>
#include <cstddef>

#define C   128
#define N0  20000
#define E1V 500000
#define E2V 500000
#define TV  500000

// ---------------- static device scratch (no allocations allowed) ----------------
__device__ __half g_y0h[(size_t)N0 * C];
__device__ __half g_y1h[(size_t)E1V * C];
__device__ __half g_y2h[(size_t)E2V * C];
__device__ float  g_a0[(size_t)N0 * C];
__device__ float  g_a1[(size_t)E1V * C];
__device__ float  g_a2[(size_t)E2V * C];
__device__ __half g_v[(size_t)E1V * C];     // part-b linear output (f16, RED target)

__device__ __forceinline__ void red2(float* p, float a, float b) {
    asm volatile("red.global.add.v2.f32 [%0], {%1,%2};"
                 :: "l"(p), "f"(a), "f"(b) : "memory");
}
__device__ __forceinline__ void redh1(__half* p, uint32_t v) {
    asm volatile("red.global.add.noftz.f16x2 [%0], %1;"
                 :: "l"(p), "r"(v) : "memory");
}
__device__ __forceinline__ uint32_t pk(float lo, float hi) {
    uint32_t d;
    asm("cvt.rn.f16x2.f32 %0, %1, %2;" : "=r"(d) : "f"(hi), "f"(lo));
    return d;
}
__device__ __forceinline__ float4 two_words(uint32_t w0, uint32_t w1) {
    float2 a = __half22float2(*(__half2*)&w0);
    float2 b = __half22float2(*(__half2*)&w1);
    return make_float4(a.x, a.y, b.x, b.y);
}
__device__ __forceinline__ float4 ldy(const __half* y, int row, int lane) {
    uint2 u = *(const uint2*)(y + (size_t)row * C + lane * 4);
    return two_words(u.x, u.y);
}
__device__ __forceinline__ uint32_t gath_word(uint32_t ua, uint32_t ub, float2 bi) {
    float2 fa = __half22float2(*(__half2*)&ua);
    float2 fb = __half22float2(*(__half2*)&ub);
    return pk(fmaxf(fa.x + fb.x + bi.x, 0.f), fmaxf(fa.y + fb.y + bi.y, 0.f));
}

// ---- f16 tile layout: 128 rows, 8 k16-groups of 8 f16x2 words, row stride 72 ----
#define ROWW 72
#define TWORDS (128 * ROWW)
__device__ __forceinline__ int widx(int r, int g, int p) { return r * ROWW + g * 8 + p; }

// permute linear words [0..7] -> [0,4,1,5,2,6,3,7] per 8-word half
__device__ __forceinline__ void permute16(const uint32_t* lin, uint32_t* w) {
#pragma unroll
    for (int h = 0; h < 2; h++) {
        const uint32_t* i8 = lin + h * 8;
        uint32_t* o = w + h * 8;
        o[0] = i8[0]; o[1] = i8[4]; o[2] = i8[1]; o[3] = i8[5];
        o[4] = i8[2]; o[5] = i8[6]; o[6] = i8[3]; o[7] = i8[7];
    }
}

// Virtual-tid loaders: vt in [0,512); row = row0 + (vt>>2), quarter q = vt&3.
__device__ __forceinline__ void ldg_tile(const float* A, int row0, int M,
                                         int vt, uint32_t* w)
{
    const int row = row0 + (vt >> 2), q = vt & 3;
    uint32_t lin[16];
#pragma unroll
    for (int j = 0; j < 16; j++) lin[j] = 0;
    if (row < M) {
        const float4* g = (const float4*)(A + (size_t)row * C + q * 32);
#pragma unroll
        for (int j = 0; j < 8; j++) {
            float4 f = g[j];
            lin[j * 2 + 0] = pk(f.x, f.y);
            lin[j * 2 + 1] = pk(f.z, f.w);
        }
    }
    permute16(lin, w);
}

__device__ __forceinline__ void ldg_gather(const __half* ya, const __half* yb,
                                           const int* iA, const int* iB,
                                           const float* binner, int row0, int M,
                                           int vt, uint32_t* w)
{
    const int r = row0 + (vt >> 2), q = vt & 3;
    uint32_t lin[16];
    if (r < M) {
        const int a = iA[r], b = iB[r];
        const uint4* ga = (const uint4*)(ya + (size_t)a * C + q * 32);
        const uint4* gb = (const uint4*)(yb + (size_t)b * C + q * 32);
        uint4 va[4], vb[4];
#pragma unroll
        for (int j = 0; j < 4; j++) { va[j] = ga[j]; vb[j] = gb[j]; }
        const float* bi = binner + q * 32;
#pragma unroll
        for (int j = 0; j < 4; j++) {
            float2 b0 = *(const float2*)(bi + j * 8 + 0);
            float2 b1 = *(const float2*)(bi + j * 8 + 2);
            float2 b2 = *(const float2*)(bi + j * 8 + 4);
            float2 b3 = *(const float2*)(bi + j * 8 + 6);
            lin[j * 4 + 0] = gath_word(va[j].x, vb[j].x, b0);
            lin[j * 4 + 1] = gath_word(va[j].y, vb[j].y, b1);
            lin[j * 4 + 2] = gath_word(va[j].z, vb[j].z, b2);
            lin[j * 4 + 3] = gath_word(va[j].w, vb[j].w, b3);
        }
    } else {
#pragma unroll
        for (int j = 0; j < 16; j++) lin[j] = 0;
    }
    permute16(lin, w);
}

__device__ __forceinline__ void sts_tile(uint32_t* buf, int vt, const uint32_t* w)
{
    const int row = vt >> 2, q = vt & 3;
    *(uint4*)(buf + widx(row, 2 * q,     0)) = make_uint4(w[0],  w[1],  w[2],  w[3]);
    *(uint4*)(buf + widx(row, 2 * q,     4)) = make_uint4(w[4],  w[5],  w[6],  w[7]);
    *(uint4*)(buf + widx(row, 2 * q + 1, 0)) = make_uint4(w[8],  w[9],  w[10], w[11]);
    *(uint4*)(buf + widx(row, 2 * q + 1, 4)) = make_uint4(w[12], w[13], w[14], w[15]);
}

// ---- 128x128x128 MMA: 8 warps (2x4), warp tile 64x32 ----------------------------
__device__ __forceinline__ void mma_f16(const uint32_t* Ab, const uint32_t* Wb,
                                        int wm, int wn, int gid, int tig,
                                        float acc[4][4][4])
{
#pragma unroll
    for (int g = 0; g < 8; g++) {
        uint32_t af[4][4], bf[4][2];
#pragma unroll
        for (int t = 0; t < 4; t++) {
            const int rl = wm + t * 16 + gid;
            uint2 lo = *(const uint2*)(Ab + widx(rl,     g, tig * 2));
            uint2 hi = *(const uint2*)(Ab + widx(rl + 8, g, tig * 2));
            af[t][0] = lo.x; af[t][1] = hi.x; af[t][2] = lo.y; af[t][3] = hi.y;
        }
#pragma unroll
        for (int tb = 0; tb < 4; tb++) {
            const int n = wn + tb * 8 + gid;
            uint2 b = *(const uint2*)(Wb + widx(n, g, tig * 2));
            bf[tb][0] = b.x; bf[tb][1] = b.y;
        }
#pragma unroll
        for (int t = 0; t < 4; t++)
#pragma unroll
            for (int tb = 0; tb < 4; tb++)
                asm("mma.sync.aligned.m16n8k16.row.col.f32.f16.f16.f32 "
                    "{%0,%1,%2,%3}, {%4,%5,%6,%7}, {%8,%9}, {%0,%1,%2,%3};"
                    : "+f"(acc[t][tb][0]), "+f"(acc[t][tb][1]),
                      "+f"(acc[t][tb][2]), "+f"(acc[t][tb][3])
                    : "r"(af[t][0]), "r"(af[t][1]), "r"(af[t][2]), "r"(af[t][3]),
                      "r"(bf[tb][0]), "r"(bf[tb][1]));
    }
}

#define ZACC(acc) do {                                                     \
    _Pragma("unroll") for (int t = 0; t < 4; t++)                          \
    _Pragma("unroll") for (int tb = 0; tb < 4; tb++)                       \
    _Pragma("unroll") for (int i = 0; i < 4; i++) acc[t][tb][i] = 0.f;     \
} while (0)

#define GEMM_SMEM (2 * TWORDS * 4)
#define FMLP_SMEM (3 * TWORDS * 4)

// ===== projection GEMM: y(half) = A(f32) @ W^T ; optional fused node-scatter =====
template<bool SCAT>
__global__ __launch_bounds__(256, 2)
void tgemm(const float* __restrict__ A, const float* __restrict__ W,
           __half* __restrict__ Cout, const int* __restrict__ sidx,
           const float* __restrict__ bscat, float* __restrict__ a0scat,
           int M, int ntiles)
{
    extern __shared__ uint32_t sm[];
    uint32_t* Wf = sm;
    uint32_t* Ab = sm + TWORDS;
    const int tid = threadIdx.x;
    const int lane = tid & 31, warp = tid >> 5;
    const int gid = lane >> 2, tig = lane & 3;
    const int wm = (warp >> 2) * 64, wn = (warp & 3) * 32;

    {
        uint32_t w[16];
        ldg_tile(W, 0, 128, tid, w);       sts_tile(Wf, tid, w);
        ldg_tile(W, 0, 128, tid + 256, w); sts_tile(Wf, tid + 256, w);
    }
    __syncthreads();

    for (int tile = blockIdx.x; tile < ntiles; tile += gridDim.x) {
        {
            uint32_t w[16];
            ldg_tile(A, tile * 128, M, tid, w);       sts_tile(Ab, tid, w);
            ldg_tile(A, tile * 128, M, tid + 256, w); sts_tile(Ab, tid + 256, w);
        }
        __syncthreads();

        float acc[4][4][4];
        ZACC(acc);
        mma_f16(Ab, Wf, wm, wn, gid, tig, acc);

#pragma unroll
        for (int t = 0; t < 4; t++) {
            const int r = tile * 128 + wm + t * 16 + gid;
            int d0 = 0, d1 = 0;
            if (SCAT) {
                if (r < M)     d0 = sidx[r];
                if (r + 8 < M) d1 = sidx[r + 8];
            }
#pragma unroll
            for (int tb = 0; tb < 4; tb++) {
                const int cc = wn + tb * 8 + tig * 2;
                float2 bs;
                if (SCAT) bs = *(const float2*)(bscat + cc);
                if (r < M) {
                    *(uint32_t*)(Cout + (size_t)r * C + cc) =
                        pk(acc[t][tb][0], acc[t][tb][1]);
                    if (SCAT)
                        red2(a0scat + (size_t)d0 * C + cc,
                             fmaxf(acc[t][tb][0] + bs.x, 0.f),
                             fmaxf(acc[t][tb][1] + bs.y, 0.f));
                }
                if (r + 8 < M) {
                    *(uint32_t*)(Cout + (size_t)(r + 8) * C + cc) =
                        pk(acc[t][tb][2], acc[t][tb][3]);
                    if (SCAT)
                        red2(a0scat + (size_t)d1 * C + cc,
                             fmaxf(acc[t][tb][2] + bs.x, 0.f),
                             fmaxf(acc[t][tb][3] + bs.y, 0.f));
                }
            }
        }
        __syncthreads();
    }
}

// ============ gather-GEMM-scatter: dst[iD[r]] += relu(ya[iA]+yb[iB]+bi) @ W^T ====
template<bool OUTH>
__global__ __launch_bounds__(256, 2)
void ggemm(const __half* __restrict__ ya, const __half* __restrict__ yb,
           const int* __restrict__ iA, const int* __restrict__ iB,
           const int* __restrict__ iD, const float* __restrict__ binner,
           const float* __restrict__ W, void* __restrict__ dst, int M, int ntiles)
{
    extern __shared__ uint32_t sm[];
    uint32_t* Wf = sm;
    uint32_t* Ab = sm + TWORDS;
    const int tid = threadIdx.x;
    const int lane = tid & 31, warp = tid >> 5;
    const int gid = lane >> 2, tig = lane & 3;
    const int wm = (warp >> 2) * 64, wn = (warp & 3) * 32;

    {
        uint32_t w[16];
        ldg_tile(W, 0, 128, tid, w);       sts_tile(Wf, tid, w);
        ldg_tile(W, 0, 128, tid + 256, w); sts_tile(Wf, tid + 256, w);
    }
    __syncthreads();

    for (int tile = blockIdx.x; tile < ntiles; tile += gridDim.x) {
        {
            uint32_t w[16];
            ldg_gather(ya, yb, iA, iB, binner, tile * 128, M, tid, w);
            sts_tile(Ab, tid, w);
            ldg_gather(ya, yb, iA, iB, binner, tile * 128, M, tid + 256, w);
            sts_tile(Ab, tid + 256, w);
        }
        __syncthreads();

        float acc[4][4][4];
        ZACC(acc);
        mma_f16(Ab, Wf, wm, wn, gid, tig, acc);

#pragma unroll
        for (int t = 0; t < 4; t++) {
            const int r = tile * 128 + wm + t * 16 + gid;
            if (r < M) {
                const size_t base = (size_t)iD[r] * C;
#pragma unroll
                for (int tb = 0; tb < 4; tb++) {
                    const int cc = wn + tb * 8 + tig * 2;
                    if (OUTH)
                        redh1((__half*)dst + base + cc, pk(acc[t][tb][0], acc[t][tb][1]));
                    else
                        red2((float*)dst + base + cc, acc[t][tb][0], acc[t][tb][1]);
                }
            }
            if (r + 8 < M) {
                const size_t base = (size_t)iD[r + 8] * C;
#pragma unroll
                for (int tb = 0; tb < 4; tb++) {
                    const int cc = wn + tb * 8 + tig * 2;
                    if (OUTH)
                        redh1((__half*)dst + base + cc, pk(acc[t][tb][2], acc[t][tb][3]));
                    else
                        red2((float*)dst + base + cc, acc[t][tb][2], acc[t][tb][3]);
                }
            }
        }
        __syncthreads();
    }
}

// ======================= fused 2-layer MLP (f16) =================================
// out = relu(Ain@Wa^T + ba) @ Wb^T + bb + R
// WITHV: Ain[r] = A[r] + v[r] + v[inv1[r]]  (v f16)
// zp: zero zp rows while streaming (restores v for the next replay)
template<bool WITHV>
__global__ __launch_bounds__(256, 2)
void fmlp(const float* __restrict__ A, const float* __restrict__ Wa,
          const float* __restrict__ ba, const float* __restrict__ Wb,
          const float* __restrict__ bb, const float* __restrict__ R,
          float* __restrict__ out, const __half* __restrict__ v,
          const int* __restrict__ inv1, __half* __restrict__ zp, int M, int ntiles)
{
    extern __shared__ uint32_t sm[];
    uint32_t* Wfa = sm;
    uint32_t* Wfb = sm + TWORDS;
    uint32_t* Ab  = sm + 2 * TWORDS;
    const int tid = threadIdx.x;
    const int lane = tid & 31, warp = tid >> 5;
    const int gid = lane >> 2, tig = lane & 3;
    const int wm = (warp >> 2) * 64, wn = (warp & 3) * 32;

    auto ld1 = [&](int row0, int vt) {
        const int r = row0 + (vt >> 2), q = vt & 3;
        uint32_t lin[16];
#pragma unroll
        for (int j = 0; j < 16; j++) lin[j] = 0;
        if (r < M) {
            float4 f[8];
            const float4* g = (const float4*)(A + (size_t)r * C + q * 32);
#pragma unroll
            for (int j = 0; j < 8; j++) f[j] = g[j];
            if (WITHV) {
                const int gi = inv1[r];
                const uint4* gv = (const uint4*)(v + (size_t)r * C + q * 32);
                const uint4* gg = (const uint4*)(v + (size_t)gi * C + q * 32);
#pragma unroll
                for (int j = 0; j < 4; j++) {
                    uint4 av = gv[j], ag = gg[j];
                    float4 s0 = two_words(av.x, av.y), s1 = two_words(av.z, av.w);
                    float4 t0 = two_words(ag.x, ag.y), t1 = two_words(ag.z, ag.w);
                    f[2 * j].x     += s0.x + t0.x; f[2 * j].y     += s0.y + t0.y;
                    f[2 * j].z     += s0.z + t0.z; f[2 * j].w     += s0.w + t0.w;
                    f[2 * j + 1].x += s1.x + t1.x; f[2 * j + 1].y += s1.y + t1.y;
                    f[2 * j + 1].z += s1.z + t1.z; f[2 * j + 1].w += s1.w + t1.w;
                }
            }
#pragma unroll
            for (int j = 0; j < 8; j++) {
                lin[j * 2 + 0] = pk(f[j].x, f[j].y);
                lin[j * 2 + 1] = pk(f[j].z, f[j].w);
            }
            if (zp) {
                uint4* z = (uint4*)(zp + (size_t)r * C + q * 32);
#pragma unroll
                for (int j = 0; j < 4; j++) z[j] = make_uint4(0, 0, 0, 0);
            }
        }
        uint32_t w[16];
        permute16(lin, w);
        sts_tile(Ab, vt, w);
    };

    {
        uint32_t w[16];
        ldg_tile(Wa, 0, 128, tid, w);       sts_tile(Wfa, tid, w);
        ldg_tile(Wa, 0, 128, tid + 256, w); sts_tile(Wfa, tid + 256, w);
        ldg_tile(Wb, 0, 128, tid, w);       sts_tile(Wfb, tid, w);
        ldg_tile(Wb, 0, 128, tid + 256, w); sts_tile(Wfb, tid + 256, w);
    }
    __syncthreads();

    for (int tile = blockIdx.x; tile < ntiles; tile += gridDim.x) {
        ld1(tile * 128, tid);
        ld1(tile * 128, tid + 256);
        __syncthreads();

        float acc[4][4][4];
        ZACC(acc);
        mma_f16(Ab, Wfa, wm, wn, gid, tig, acc);
        __syncthreads();                 // all warps done reading A

        {   // hidden = relu(acc + ba) -> back into Ab
            const int gbase = wn >> 4;
#pragma unroll
            for (int t = 0; t < 4; t++) {
                const int rl = wm + t * 16 + gid;
#pragma unroll
                for (int tb = 0; tb < 4; tb++) {
                    const int cc = wn + tb * 8 + tig * 2;
                    const int g = gbase + (tb >> 1);
                    const int p = 2 * tig + (tb & 1);
                    float2 b2 = *(const float2*)(ba + cc);
                    Ab[widx(rl,     g, p)] = pk(fmaxf(acc[t][tb][0] + b2.x, 0.f),
                                                fmaxf(acc[t][tb][1] + b2.y, 0.f));
                    Ab[widx(rl + 8, g, p)] = pk(fmaxf(acc[t][tb][2] + b2.x, 0.f),
                                                fmaxf(acc[t][tb][3] + b2.y, 0.f));
                }
            }
        }
        __syncthreads();

        ZACC(acc);
        mma_f16(Ab, Wfb, wm, wn, gid, tig, acc);

#pragma unroll
        for (int t = 0; t < 4; t++) {
            const int r = tile * 128 + wm + t * 16 + gid;
#pragma unroll
            for (int tb = 0; tb < 4; tb++) {
                const int cc = wn + tb * 8 + tig * 2;
                float2 bb2 = *(const float2*)(bb + cc);
                if (r < M) {
                    float2 o = *(const float2*)(R + (size_t)r * C + cc);
                    *(float2*)(out + (size_t)r * C + cc) =
                        make_float2(acc[t][tb][0] + bb2.x + o.x,
                                    acc[t][tb][1] + bb2.y + o.y);
                }
                if (r + 8 < M) {
                    float2 o = *(const float2*)(R + (size_t)(r + 8) * C + cc);
                    *(float2*)(out + (size_t)(r + 8) * C + cc) =
                        make_float2(acc[t][tb][2] + bb2.x + o.x,
                                    acc[t][tb][3] + bb2.y + o.y);
                }
            }
        }
        __syncthreads();                 // done reading hidden before next ld
    }
}

// ---- edge: dst[r] = relu(y[s]+y[e]+bi) + x[r] + b1 + b2 -------------------------
__global__ void edge_kernel(const __half* __restrict__ y, const int* __restrict__ s,
                            const int* __restrict__ e, const float* __restrict__ bi,
                            const float* __restrict__ x, const float* __restrict__ b1,
                            const float* __restrict__ b2, float* __restrict__ dst, int M)
{
    const int w = (blockIdx.x * blockDim.x + threadIdx.x) >> 5;
    const int lane = threadIdx.x & 31;
    if (w >= M) return;
    float4 va = ldy(y, s[w], lane);
    float4 vb = ldy(y, e[w], lane);
    float4 bb = *(const float4*)(bi + lane * 4);
    float4 c1 = *(const float4*)(b1 + lane * 4);
    float4 c2 = *(const float4*)(b2 + lane * 4);
    float4 xx = *(const float4*)(x + (size_t)w * C + lane * 4);
    float4 o;
    o.x = fmaxf(va.x + vb.x + bb.x, 0.f) + xx.x + c1.x + c2.x;
    o.y = fmaxf(va.y + vb.y + bb.y, 0.f) + xx.y + c1.y + c2.y;
    o.z = fmaxf(va.z + vb.z + bb.z, 0.f) + xx.z + c1.z + c2.z;
    o.w = fmaxf(va.w + vb.w + bb.w, 0.f) + xx.w + c1.w + c2.w;
    *(float4*)(dst + (size_t)w * C + lane * 4) = o;
}

// ================================================================================
template<bool SCAT>
static inline void run_tgemm(const float* A, const float* W, __half* Co,
                             const int* sidx, const float* bscat, float* a0, int M)
{
    int nt = (M + 127) / 128;
    int grid = nt < 296 ? nt : 296;
    cudaFuncSetAttribute(tgemm<SCAT>, cudaFuncAttributeMaxDynamicSharedMemorySize, GEMM_SMEM);
    tgemm<SCAT><<<grid, 256, GEMM_SMEM>>>(A, W, Co, sidx, bscat, a0, M, nt);
}

template<bool OUTH>
static inline void run_ggemm(const __half* ya, const __half* yb, const int* iA,
                             const int* iB, const int* iD, const float* bi,
                             const float* W, void* dst, int M)
{
    int nt = (M + 127) / 128;
    int grid = nt < 296 ? nt : 296;
    cudaFuncSetAttribute(ggemm<OUTH>, cudaFuncAttributeMaxDynamicSharedMemorySize, GEMM_SMEM);
    ggemm<OUTH><<<grid, 256, GEMM_SMEM>>>(ya, yb, iA, iB, iD, bi, W, dst, M, nt);
}

template<bool WITHV>
static inline void run_fmlp(const float* A, const float* Wa, const float* ba,
                            const float* Wb, const float* bb, const float* R,
                            float* out, const __half* v, const int* inv1,
                            __half* zp, int M)
{
    int nt = (M + 127) / 128;
    int grid = nt < 296 ? nt : 296;
    cudaFuncSetAttribute(fmlp<WITHV>, cudaFuncAttributeMaxDynamicSharedMemorySize, FMLP_SMEM);
    fmlp<WITHV><<<grid, 256, FMLP_SMEM>>>(A, Wa, ba, Wb, bb, R, out, v, inv1, zp, M, nt);
}

extern "C" void kernel_launch(void* const* d_in, const int* in_sizes, int n_in,
                              void* d_out, int out_size)
{
    (void)in_sizes; (void)n_in; (void)out_size;
    const float* x0   = (const float*)d_in[0];
    const float* x1   = (const float*)d_in[1];
    const float* x2   = (const float*)d_in[2];
    const int*   ei1  = (const int*)d_in[3];
    const int*   ei2  = (const int*)d_in[4];
    const int*   t111 = (const int*)d_in[5];
    const int*   t222 = (const int*)d_in[6];
    const int*   t112 = (const int*)d_in[7];
    const int*   inv1 = (const int*)d_in[8];
    const float* WiW  = (const float*)d_in[10]; const float* Wib  = (const float*)d_in[11];
    const float* l111W= (const float*)d_in[12]; const float* l111b= (const float*)d_in[13];
    const float* l222W= (const float*)d_in[14]; const float* l222b= (const float*)d_in[15];
    const float* l211W= (const float*)d_in[16]; const float* l211b= (const float*)d_in[17];
    const float* m0aW = (const float*)d_in[18]; const float* m0ab = (const float*)d_in[19];
    const float* m0bW = (const float*)d_in[20]; const float* m0bb = (const float*)d_in[21];
    const float* m1aW = (const float*)d_in[22]; const float* m1ab = (const float*)d_in[23];
    const float* m1bW = (const float*)d_in[24]; const float* m1bb = (const float*)d_in[25];
    const float* m2aW = (const float*)d_in[26]; const float* m2ab = (const float*)d_in[27];
    const float* m2bW = (const float*)d_in[28]; const float* m2bb = (const float*)d_in[29];
    float* out = (float*)d_out;

    __half *y0, *y1, *y2, *v;
    float *a0, *a1, *a2;
    cudaGetSymbolAddress((void**)&y0, g_y0h);
    cudaGetSymbolAddress((void**)&y1, g_y1h);
    cudaGetSymbolAddress((void**)&y2, g_y2h);
    cudaGetSymbolAddress((void**)&a0, g_a0);
    cudaGetSymbolAddress((void**)&a1, g_a1);
    cudaGetSymbolAddress((void**)&a2, g_a2);
    cudaGetSymbolAddress((void**)&v,  g_v);

    const dim3 blk(256);
    auto eg = [](int M) { return dim3((unsigned)((M + 7) / 8)); };

    // a0 starts as x0 (residual fold). v starts zero (globals zeroed at init;
    // fmlp2 re-zeroes it every replay after fmlp1 consumed it).
    cudaMemcpyAsync(a0, x0, (size_t)N0 * C * sizeof(float), cudaMemcpyDeviceToDevice, 0); // 1

    // projections; x1/x2 projections fuse the node scatter into a0 (L2-resident)
    run_tgemm<false>(x0, WiW, y0, nullptr, nullptr, nullptr, N0);           // 2
    run_tgemm<true >(x1, WiW, y1, ei1, Wib, a0, E1V);                       // 3
    run_tgemm<true >(x2, WiW, y2, ei2, Wib, a0, E2V);                       // 4

    // edge init of a1 with residual x and folded linear biases
    edge_kernel<<<eg(E1V), blk>>>(y0, ei1, ei1 + E1V, Wib, x1, l111b, l211b, a1, E1V); // 5

    // (1,1,1): a1[t0] += L111(relu(y1[t1]+y1[t2]+b))          <- ncu slot 6
    run_ggemm<false>(y1, y1, t111 + TV, t111 + 2 * TV, t111, Wib, l111W, a1, TV);

    edge_kernel<<<eg(E2V), blk>>>(y0, ei2, ei2 + E2V, Wib, x2, l222b, l211b, a2, E2V); // 7

    // (2,2,2): a2[t0] += L222(relu(y2[t1]+y2[t2]+b))
    run_ggemm<false>(y2, y2, t222 + TV, t222 + 2 * TV, t222, Wib, l222W, a2, TV);
    // (1,1,2) part a: a2[t2] += L211(relu(y1[t0]+y1[t1]+b))
    run_ggemm<false>(y1, y1, t112, t112 + TV, t112 + 2 * TV, Wib, l211W, a2, TV);
    // (1,1,2) part b: v[t0] += L211(relu(y1[t1]+y2[t2]+b))   (f16 RED)
    run_ggemm<true>(y1, y2, t112 + TV, t112 + 2 * TV, t112, Wib, l211W, v, TV);

    // fused output MLPs + residual; fmlp1 folds v + v[inv1]; fmlp2 re-zeroes v
    run_fmlp<false>(a0, m0aW, m0ab, m0bW, m0bb, x0, out, nullptr, nullptr, nullptr, N0);
    run_fmlp<true >(a1, m1aW, m1ab, m1bW, m1bb, x1, out + (size_t)N0 * C,
                    v, inv1, nullptr, E1V);
    run_fmlp<false>(a2, m2aW, m2ab, m2bW, m2bb, x2, out + ((size_t)N0 + E1V) * C,
                    nullptr, nullptr, v, E2V);
}

// round 17
// speedup vs baseline: 1.2143x; 1.0175x over previous
#include <cuda_runtime.h>
#include <cuda_fp16.h>
#include <cstdint>
#include <cstddef>

#define C   128
#define N0  20000
#define E1V 500000
#define E2V 500000
#define TV  500000

// ---------------- static device scratch (no allocations allowed) ----------------
__device__ __half g_y0h[(size_t)N0 * C];
__device__ __half g_y1h[(size_t)E1V * C];
__device__ __half g_y2h[(size_t)E2V * C];
__device__ float  g_a0[(size_t)N0 * C];     // level-0 accumulator (fp32, small)
__device__ __half g_a1h[(size_t)E1V * C];   // level-1/2 accumulators in f16
__device__ __half g_a2h[(size_t)E2V * C];
__device__ __half g_v[(size_t)E1V * C];     // part-b linear output (f16, RED target)

__device__ __forceinline__ void red2(float* p, float a, float b) {
    asm volatile("red.global.add.v2.f32 [%0], {%1,%2};"
                 :: "l"(p), "f"(a), "f"(b) : "memory");
}
__device__ __forceinline__ void redh1(__half* p, uint32_t v) {
    asm volatile("red.global.add.noftz.f16x2 [%0], %1;"
                 :: "l"(p), "r"(v) : "memory");
}
__device__ __forceinline__ uint32_t pk(float lo, float hi) {
    uint32_t d;
    asm("cvt.rn.f16x2.f32 %0, %1, %2;" : "=r"(d) : "f"(hi), "f"(lo));
    return d;
}
__device__ __forceinline__ float4 two_words(uint32_t w0, uint32_t w1) {
    float2 a = __half22float2(*(__half2*)&w0);
    float2 b = __half22float2(*(__half2*)&w1);
    return make_float4(a.x, a.y, b.x, b.y);
}
__device__ __forceinline__ float4 ldy(const __half* y, int row, int lane) {
    uint2 u = *(const uint2*)(y + (size_t)row * C + lane * 4);
    return two_words(u.x, u.y);
}
__device__ __forceinline__ uint32_t gath_word(uint32_t ua, uint32_t ub, float2 bi) {
    float2 fa = __half22float2(*(__half2*)&ua);
    float2 fb = __half22float2(*(__half2*)&ub);
    return pk(fmaxf(fa.x + fb.x + bi.x, 0.f), fmaxf(fa.y + fb.y + bi.y, 0.f));
}

// ---- f16 tile layout: 128 rows, 8 k16-groups of 8 f16x2 words, row stride 72 ----
#define ROWW 72
#define TWORDS (128 * ROWW)
__device__ __forceinline__ int widx(int r, int g, int p) { return r * ROWW + g * 8 + p; }

// permute linear words [0..7] -> [0,4,1,5,2,6,3,7] per 8-word half
__device__ __forceinline__ void permute16(const uint32_t* lin, uint32_t* w) {
#pragma unroll
    for (int h = 0; h < 2; h++) {
        const uint32_t* i8 = lin + h * 8;
        uint32_t* o = w + h * 8;
        o[0] = i8[0]; o[1] = i8[4]; o[2] = i8[1]; o[3] = i8[5];
        o[4] = i8[2]; o[5] = i8[6]; o[6] = i8[3]; o[7] = i8[7];
    }
}

// Virtual-tid loaders: vt in [0,512); row = row0 + (vt>>2), quarter q = vt&3.
__device__ __forceinline__ void ldg_tile(const float* A, int row0, int M,
                                         int vt, uint32_t* w)
{
    const int row = row0 + (vt >> 2), q = vt & 3;
    uint32_t lin[16];
#pragma unroll
    for (int j = 0; j < 16; j++) lin[j] = 0;
    if (row < M) {
        const float4* g = (const float4*)(A + (size_t)row * C + q * 32);
#pragma unroll
        for (int j = 0; j < 8; j++) {
            float4 f = g[j];
            lin[j * 2 + 0] = pk(f.x, f.y);
            lin[j * 2 + 1] = pk(f.z, f.w);
        }
    }
    permute16(lin, w);
}

__device__ __forceinline__ void ldg_gather(const __half* ya, const __half* yb,
                                           const int* iA, const int* iB,
                                           const float* binner, int row0, int M,
                                           int vt, uint32_t* w)
{
    const int r = row0 + (vt >> 2), q = vt & 3;
    uint32_t lin[16];
    if (r < M) {
        const int a = iA[r], b = iB[r];
        const uint4* ga = (const uint4*)(ya + (size_t)a * C + q * 32);
        const uint4* gb = (const uint4*)(yb + (size_t)b * C + q * 32);
        uint4 va[4], vb[4];
#pragma unroll
        for (int j = 0; j < 4; j++) { va[j] = ga[j]; vb[j] = gb[j]; }
        const float* bi = binner + q * 32;
#pragma unroll
        for (int j = 0; j < 4; j++) {
            float2 b0 = *(const float2*)(bi + j * 8 + 0);
            float2 b1 = *(const float2*)(bi + j * 8 + 2);
            float2 b2 = *(const float2*)(bi + j * 8 + 4);
            float2 b3 = *(const float2*)(bi + j * 8 + 6);
            lin[j * 4 + 0] = gath_word(va[j].x, vb[j].x, b0);
            lin[j * 4 + 1] = gath_word(va[j].y, vb[j].y, b1);
            lin[j * 4 + 2] = gath_word(va[j].z, vb[j].z, b2);
            lin[j * 4 + 3] = gath_word(va[j].w, vb[j].w, b3);
        }
    } else {
#pragma unroll
        for (int j = 0; j < 16; j++) lin[j] = 0;
    }
    permute16(lin, w);
}

__device__ __forceinline__ void sts_tile(uint32_t* buf, int vt, const uint32_t* w)
{
    const int row = vt >> 2, q = vt & 3;
    *(uint4*)(buf + widx(row, 2 * q,     0)) = make_uint4(w[0],  w[1],  w[2],  w[3]);
    *(uint4*)(buf + widx(row, 2 * q,     4)) = make_uint4(w[4],  w[5],  w[6],  w[7]);
    *(uint4*)(buf + widx(row, 2 * q + 1, 0)) = make_uint4(w[8],  w[9],  w[10], w[11]);
    *(uint4*)(buf + widx(row, 2 * q + 1, 4)) = make_uint4(w[12], w[13], w[14], w[15]);
}

// ---- 128x128x128 MMA: 8 warps (2x4), warp tile 64x32 ----------------------------
__device__ __forceinline__ void mma_f16(const uint32_t* Ab, const uint32_t* Wb,
                                        int wm, int wn, int gid, int tig,
                                        float acc[4][4][4])
{
#pragma unroll
    for (int g = 0; g < 8; g++) {
        uint32_t af[4][4], bf[4][2];
#pragma unroll
        for (int t = 0; t < 4; t++) {
            const int rl = wm + t * 16 + gid;
            uint2 lo = *(const uint2*)(Ab + widx(rl,     g, tig * 2));
            uint2 hi = *(const uint2*)(Ab + widx(rl + 8, g, tig * 2));
            af[t][0] = lo.x; af[t][1] = hi.x; af[t][2] = lo.y; af[t][3] = hi.y;
        }
#pragma unroll
        for (int tb = 0; tb < 4; tb++) {
            const int n = wn + tb * 8 + gid;
            uint2 b = *(const uint2*)(Wb + widx(n, g, tig * 2));
            bf[tb][0] = b.x; bf[tb][1] = b.y;
        }
#pragma unroll
        for (int t = 0; t < 4; t++)
#pragma unroll
            for (int tb = 0; tb < 4; tb++)
                asm("mma.sync.aligned.m16n8k16.row.col.f32.f16.f16.f32 "
                    "{%0,%1,%2,%3}, {%4,%5,%6,%7}, {%8,%9}, {%0,%1,%2,%3};"
                    : "+f"(acc[t][tb][0]), "+f"(acc[t][tb][1]),
                      "+f"(acc[t][tb][2]), "+f"(acc[t][tb][3])
                    : "r"(af[t][0]), "r"(af[t][1]), "r"(af[t][2]), "r"(af[t][3]),
                      "r"(bf[tb][0]), "r"(bf[tb][1]));
    }
}

#define ZACC(acc) do {                                                     \
    _Pragma("unroll") for (int t = 0; t < 4; t++)                          \
    _Pragma("unroll") for (int tb = 0; tb < 4; tb++)                       \
    _Pragma("unroll") for (int i = 0; i < 4; i++) acc[t][tb][i] = 0.f;     \
} while (0)

#define GEMM_SMEM (2 * TWORDS * 4)
#define FMLP_SMEM (3 * TWORDS * 4)

// ===== projection GEMM: y(half) = A(f32) @ W^T ; optional fused node-scatter =====
template<bool SCAT>
__global__ __launch_bounds__(256, 2)
void tgemm(const float* __restrict__ A, const float* __restrict__ W,
           __half* __restrict__ Cout, const int* __restrict__ sidx,
           const float* __restrict__ bscat, float* __restrict__ a0scat,
           int M, int ntiles)
{
    extern __shared__ uint32_t sm[];
    uint32_t* Wf = sm;
    uint32_t* Ab = sm + TWORDS;
    const int tid = threadIdx.x;
    const int lane = tid & 31, warp = tid >> 5;
    const int gid = lane >> 2, tig = lane & 3;
    const int wm = (warp >> 2) * 64, wn = (warp & 3) * 32;

    {
        uint32_t w[16];
        ldg_tile(W, 0, 128, tid, w);       sts_tile(Wf, tid, w);
        ldg_tile(W, 0, 128, tid + 256, w); sts_tile(Wf, tid + 256, w);
    }
    __syncthreads();

    for (int tile = blockIdx.x; tile < ntiles; tile += gridDim.x) {
        {
            uint32_t w[16];
            ldg_tile(A, tile * 128, M, tid, w);       sts_tile(Ab, tid, w);
            ldg_tile(A, tile * 128, M, tid + 256, w); sts_tile(Ab, tid + 256, w);
        }
        __syncthreads();

        float acc[4][4][4];
        ZACC(acc);
        mma_f16(Ab, Wf, wm, wn, gid, tig, acc);

#pragma unroll
        for (int t = 0; t < 4; t++) {
            const int r = tile * 128 + wm + t * 16 + gid;
            int d0 = 0, d1 = 0;
            if (SCAT) {
                if (r < M)     d0 = sidx[r];
                if (r + 8 < M) d1 = sidx[r + 8];
            }
#pragma unroll
            for (int tb = 0; tb < 4; tb++) {
                const int cc = wn + tb * 8 + tig * 2;
                float2 bs;
                if (SCAT) bs = *(const float2*)(bscat + cc);
                if (r < M) {
                    *(uint32_t*)(Cout + (size_t)r * C + cc) =
                        pk(acc[t][tb][0], acc[t][tb][1]);
                    if (SCAT)
                        red2(a0scat + (size_t)d0 * C + cc,
                             fmaxf(acc[t][tb][0] + bs.x, 0.f),
                             fmaxf(acc[t][tb][1] + bs.y, 0.f));
                }
                if (r + 8 < M) {
                    *(uint32_t*)(Cout + (size_t)(r + 8) * C + cc) =
                        pk(acc[t][tb][2], acc[t][tb][3]);
                    if (SCAT)
                        red2(a0scat + (size_t)d1 * C + cc,
                             fmaxf(acc[t][tb][2] + bs.x, 0.f),
                             fmaxf(acc[t][tb][3] + bs.y, 0.f));
                }
            }
        }
        __syncthreads();
    }
}

// ============ gather-GEMM-scatter: dst[iD[r]] += relu(ya[iA]+yb[iB]+bi) @ W^T ====
// dst is __half; f16x2 vector reductions.
__global__ __launch_bounds__(256, 2)
void ggemm(const __half* __restrict__ ya, const __half* __restrict__ yb,
           const int* __restrict__ iA, const int* __restrict__ iB,
           const int* __restrict__ iD, const float* __restrict__ binner,
           const float* __restrict__ W, __half* __restrict__ dst, int M, int ntiles)
{
    extern __shared__ uint32_t sm[];
    uint32_t* Wf = sm;
    uint32_t* Ab = sm + TWORDS;
    const int tid = threadIdx.x;
    const int lane = tid & 31, warp = tid >> 5;
    const int gid = lane >> 2, tig = lane & 3;
    const int wm = (warp >> 2) * 64, wn = (warp & 3) * 32;

    {
        uint32_t w[16];
        ldg_tile(W, 0, 128, tid, w);       sts_tile(Wf, tid, w);
        ldg_tile(W, 0, 128, tid + 256, w); sts_tile(Wf, tid + 256, w);
    }
    __syncthreads();

    for (int tile = blockIdx.x; tile < ntiles; tile += gridDim.x) {
        {
            uint32_t w[16];
            ldg_gather(ya, yb, iA, iB, binner, tile * 128, M, tid, w);
            sts_tile(Ab, tid, w);
            ldg_gather(ya, yb, iA, iB, binner, tile * 128, M, tid + 256, w);
            sts_tile(Ab, tid + 256, w);
        }
        __syncthreads();

        float acc[4][4][4];
        ZACC(acc);
        mma_f16(Ab, Wf, wm, wn, gid, tig, acc);

#pragma unroll
        for (int t = 0; t < 4; t++) {
            const int r = tile * 128 + wm + t * 16 + gid;
            if (r < M) {
                const size_t base = (size_t)iD[r] * C;
#pragma unroll
                for (int tb = 0; tb < 4; tb++) {
                    const int cc = wn + tb * 8 + tig * 2;
                    redh1(dst + base + cc, pk(acc[t][tb][0], acc[t][tb][1]));
                }
            }
            if (r + 8 < M) {
                const size_t base = (size_t)iD[r + 8] * C;
#pragma unroll
                for (int tb = 0; tb < 4; tb++) {
                    const int cc = wn + tb * 8 + tig * 2;
                    redh1(dst + base + cc, pk(acc[t][tb][2], acc[t][tb][3]));
                }
            }
        }
        __syncthreads();
    }
}

// ======================= fused 2-layer MLP (f16) =================================
// MLP input per row r:
//   AH ? (f16 Ah[r]) : (fp32 Af[r])
// + (WITHX) X[r]
// + (WITHV) v[r] + v[inv1[r]]
// out = relu(in@Wa^T + ba) @ Wb^T + bb + X
// zp: zero zp rows while streaming (restores v for the next replay)
template<bool AH, bool WITHX, bool WITHV>
__global__ __launch_bounds__(256, 2)
void fmlp(const void* __restrict__ Ain, const float* __restrict__ X,
          const float* __restrict__ Wa, const float* __restrict__ ba,
          const float* __restrict__ Wb, const float* __restrict__ bb,
          float* __restrict__ out, const __half* __restrict__ v,
          const int* __restrict__ inv1, __half* __restrict__ zp, int M, int ntiles)
{
    extern __shared__ uint32_t sm[];
    uint32_t* Wfa = sm;
    uint32_t* Wfb = sm + TWORDS;
    uint32_t* Ab  = sm + 2 * TWORDS;
    const int tid = threadIdx.x;
    const int lane = tid & 31, warp = tid >> 5;
    const int gid = lane >> 2, tig = lane & 3;
    const int wm = (warp >> 2) * 64, wn = (warp & 3) * 32;

    auto ld1 = [&](int row0, int vt) {
        const int r = row0 + (vt >> 2), q = vt & 3;
        uint32_t lin[16];
#pragma unroll
        for (int j = 0; j < 16; j++) lin[j] = 0;
        if (r < M) {
            float4 f[8];
            if (AH) {
                const uint4* ga = (const uint4*)((const __half*)Ain + (size_t)r * C + q * 32);
#pragma unroll
                for (int j = 0; j < 4; j++) {
                    uint4 u = ga[j];
                    f[2 * j]     = two_words(u.x, u.y);
                    f[2 * j + 1] = two_words(u.z, u.w);
                }
            } else {
                const float4* ga = (const float4*)((const float*)Ain + (size_t)r * C + q * 32);
#pragma unroll
                for (int j = 0; j < 8; j++) f[j] = ga[j];
            }
            if (WITHX) {
                const float4* gx = (const float4*)(X + (size_t)r * C + q * 32);
#pragma unroll
                for (int j = 0; j < 8; j++) {
                    float4 xv = gx[j];
                    f[j].x += xv.x; f[j].y += xv.y; f[j].z += xv.z; f[j].w += xv.w;
                }
            }
            if (WITHV) {
                const int gi = inv1[r];
                const uint4* gv = (const uint4*)(v + (size_t)r * C + q * 32);
                const uint4* gg = (const uint4*)(v + (size_t)gi * C + q * 32);
#pragma unroll
                for (int j = 0; j < 4; j++) {
                    uint4 av = gv[j], ag = gg[j];
                    float4 s0 = two_words(av.x, av.y), s1 = two_words(av.z, av.w);
                    float4 t0 = two_words(ag.x, ag.y), t1 = two_words(ag.z, ag.w);
                    f[2 * j].x     += s0.x + t0.x; f[2 * j].y     += s0.y + t0.y;
                    f[2 * j].z     += s0.z + t0.z; f[2 * j].w     += s0.w + t0.w;
                    f[2 * j + 1].x += s1.x + t1.x; f[2 * j + 1].y += s1.y + t1.y;
                    f[2 * j + 1].z += s1.z + t1.z; f[2 * j + 1].w += s1.w + t1.w;
                }
            }
#pragma unroll
            for (int j = 0; j < 8; j++) {
                lin[j * 2 + 0] = pk(f[j].x, f[j].y);
                lin[j * 2 + 1] = pk(f[j].z, f[j].w);
            }
            if (zp) {
                uint4* z = (uint4*)(zp + (size_t)r * C + q * 32);
#pragma unroll
                for (int j = 0; j < 4; j++) z[j] = make_uint4(0, 0, 0, 0);
            }
        }
        uint32_t w[16];
        permute16(lin, w);
        sts_tile(Ab, vt, w);
    };

    {
        uint32_t w[16];
        ldg_tile(Wa, 0, 128, tid, w);       sts_tile(Wfa, tid, w);
        ldg_tile(Wa, 0, 128, tid + 256, w); sts_tile(Wfa, tid + 256, w);
        ldg_tile(Wb, 0, 128, tid, w);       sts_tile(Wfb, tid, w);
        ldg_tile(Wb, 0, 128, tid + 256, w); sts_tile(Wfb, tid + 256, w);
    }
    __syncthreads();

    for (int tile = blockIdx.x; tile < ntiles; tile += gridDim.x) {
        ld1(tile * 128, tid);
        ld1(tile * 128, tid + 256);
        __syncthreads();

        float acc[4][4][4];
        ZACC(acc);
        mma_f16(Ab, Wfa, wm, wn, gid, tig, acc);
        __syncthreads();                 // all warps done reading A

        {   // hidden = relu(acc + ba) -> back into Ab
            const int gbase = wn >> 4;
#pragma unroll
            for (int t = 0; t < 4; t++) {
                const int rl = wm + t * 16 + gid;
#pragma unroll
                for (int tb = 0; tb < 4; tb++) {
                    const int cc = wn + tb * 8 + tig * 2;
                    const int g = gbase + (tb >> 1);
                    const int p = 2 * tig + (tb & 1);
                    float2 b2 = *(const float2*)(ba + cc);
                    Ab[widx(rl,     g, p)] = pk(fmaxf(acc[t][tb][0] + b2.x, 0.f),
                                                fmaxf(acc[t][tb][1] + b2.y, 0.f));
                    Ab[widx(rl + 8, g, p)] = pk(fmaxf(acc[t][tb][2] + b2.x, 0.f),
                                                fmaxf(acc[t][tb][3] + b2.y, 0.f));
                }
            }
        }
        __syncthreads();

        ZACC(acc);
        mma_f16(Ab, Wfb, wm, wn, gid, tig, acc);

#pragma unroll
        for (int t = 0; t < 4; t++) {
            const int r = tile * 128 + wm + t * 16 + gid;
#pragma unroll
            for (int tb = 0; tb < 4; tb++) {
                const int cc = wn + tb * 8 + tig * 2;
                float2 bb2 = *(const float2*)(bb + cc);
                if (r < M) {
                    float2 o = *(const float2*)(X + (size_t)r * C + cc);
                    *(float2*)(out + (size_t)r * C + cc) =
                        make_float2(acc[t][tb][0] + bb2.x + o.x,
                                    acc[t][tb][1] + bb2.y + o.y);
                }
                if (r + 8 < M) {
                    float2 o = *(const float2*)(X + (size_t)(r + 8) * C + cc);
                    *(float2*)(out + (size_t)(r + 8) * C + cc) =
                        make_float2(acc[t][tb][2] + bb2.x + o.x,
                                    acc[t][tb][3] + bb2.y + o.y);
                }
            }
        }
        __syncthreads();                 // done reading hidden before next ld
    }
}

// ---- edge init (f16 dst, no x): dst[r] = relu(y[s]+y[e]+bi) + b1 + b2 -----------
__global__ void edge_kernel(const __half* __restrict__ y, const int* __restrict__ s,
                            const int* __restrict__ e, const float* __restrict__ bi,
                            const float* __restrict__ b1, const float* __restrict__ b2,
                            __half* __restrict__ dst, int M)
{
    const int w = (blockIdx.x * blockDim.x + threadIdx.x) >> 5;
    const int lane = threadIdx.x & 31;
    if (w >= M) return;
    float4 va = ldy(y, s[w], lane);
    float4 vb = ldy(y, e[w], lane);
    float4 bb = *(const float4*)(bi + lane * 4);
    float4 c1 = *(const float4*)(b1 + lane * 4);
    float4 c2 = *(const float4*)(b2 + lane * 4);
    float4 o;
    o.x = fmaxf(va.x + vb.x + bb.x, 0.f) + c1.x + c2.x;
    o.y = fmaxf(va.y + vb.y + bb.y, 0.f) + c1.y + c2.y;
    o.z = fmaxf(va.z + vb.z + bb.z, 0.f) + c1.z + c2.z;
    o.w = fmaxf(va.w + vb.w + bb.w, 0.f) + c1.w + c2.w;
    *(uint2*)(dst + (size_t)w * C + lane * 4) = make_uint2(pk(o.x, o.y), pk(o.z, o.w));
}

// ================================================================================
template<bool SCAT>
static inline void run_tgemm(const float* A, const float* W, __half* Co,
                             const int* sidx, const float* bscat, float* a0, int M)
{
    int nt = (M + 127) / 128;
    int grid = nt < 296 ? nt : 296;
    cudaFuncSetAttribute(tgemm<SCAT>, cudaFuncAttributeMaxDynamicSharedMemorySize, GEMM_SMEM);
    tgemm<SCAT><<<grid, 256, GEMM_SMEM>>>(A, W, Co, sidx, bscat, a0, M, nt);
}

static inline void run_ggemm(const __half* ya, const __half* yb, const int* iA,
                             const int* iB, const int* iD, const float* bi,
                             const float* W, __half* dst, int M)
{
    int nt = (M + 127) / 128;
    int grid = nt < 296 ? nt : 296;
    cudaFuncSetAttribute(ggemm, cudaFuncAttributeMaxDynamicSharedMemorySize, GEMM_SMEM);
    ggemm<<<grid, 256, GEMM_SMEM>>>(ya, yb, iA, iB, iD, bi, W, dst, M, nt);
}

template<bool AH, bool WITHX, bool WITHV>
static inline void run_fmlp(const void* Ain, const float* X, const float* Wa,
                            const float* ba, const float* Wb, const float* bb,
                            float* out, const __half* v, const int* inv1,
                            __half* zp, int M)
{
    int nt = (M + 127) / 128;
    int grid = nt < 296 ? nt : 296;
    cudaFuncSetAttribute(fmlp<AH, WITHX, WITHV>,
                         cudaFuncAttributeMaxDynamicSharedMemorySize, FMLP_SMEM);
    fmlp<AH, WITHX, WITHV><<<grid, 256, FMLP_SMEM>>>(Ain, X, Wa, ba, Wb, bb, out,
                                                     v, inv1, zp, M, nt);
}

extern "C" void kernel_launch(void* const* d_in, const int* in_sizes, int n_in,
                              void* d_out, int out_size)
{
    (void)in_sizes; (void)n_in; (void)out_size;
    const float* x0   = (const float*)d_in[0];
    const float* x1   = (const float*)d_in[1];
    const float* x2   = (const float*)d_in[2];
    const int*   ei1  = (const int*)d_in[3];
    const int*   ei2  = (const int*)d_in[4];
    const int*   t111 = (const int*)d_in[5];
    const int*   t222 = (const int*)d_in[6];
    const int*   t112 = (const int*)d_in[7];
    const int*   inv1 = (const int*)d_in[8];
    const float* WiW  = (const float*)d_in[10]; const float* Wib  = (const float*)d_in[11];
    const float* l111W= (const float*)d_in[12]; const float* l111b= (const float*)d_in[13];
    const float* l222W= (const float*)d_in[14]; const float* l222b= (const float*)d_in[15];
    const float* l211W= (const float*)d_in[16]; const float* l211b= (const float*)d_in[17];
    const float* m0aW = (const float*)d_in[18]; const float* m0ab = (const float*)d_in[19];
    const float* m0bW = (const float*)d_in[20]; const float* m0bb = (const float*)d_in[21];
    const float* m1aW = (const float*)d_in[22]; const float* m1ab = (const float*)d_in[23];
    const float* m1bW = (const float*)d_in[24]; const float* m1bb = (const float*)d_in[25];
    const float* m2aW = (const float*)d_in[26]; const float* m2ab = (const float*)d_in[27];
    const float* m2bW = (const float*)d_in[28]; const float* m2bb = (const float*)d_in[29];
    float* out = (float*)d_out;

    __half *y0, *y1, *y2, *a1h, *a2h, *v;
    float *a0;
    cudaGetSymbolAddress((void**)&y0,  g_y0h);
    cudaGetSymbolAddress((void**)&y1,  g_y1h);
    cudaGetSymbolAddress((void**)&y2,  g_y2h);
    cudaGetSymbolAddress((void**)&a0,  g_a0);
    cudaGetSymbolAddress((void**)&a1h, g_a1h);
    cudaGetSymbolAddress((void**)&a2h, g_a2h);
    cudaGetSymbolAddress((void**)&v,   g_v);

    const dim3 blk(256);
    auto eg = [](int M) { return dim3((unsigned)((M + 7) / 8)); };

    // a0 starts as x0 (residual fold). v starts zero (globals zeroed at init;
    // fmlp2 re-zeroes it every replay after fmlp1 consumed it). a1h/a2h are
    // fully overwritten by the edge kernels each replay.
    cudaMemcpyAsync(a0, x0, (size_t)N0 * C * sizeof(float), cudaMemcpyDeviceToDevice, 0);

    // projections; x1/x2 projections fuse the node scatter into a0 (L2-resident)
    run_tgemm<false>(x0, WiW, y0, nullptr, nullptr, nullptr, N0);           // k1
    run_tgemm<true >(x1, WiW, y1, ei1, Wib, a0, E1V);                       // k2
    run_tgemm<true >(x2, WiW, y2, ei2, Wib, a0, E2V);                       // k3

    // edge init of a1h/a2h (f16, x folded into fmlp instead)
    edge_kernel<<<eg(E1V), blk>>>(y0, ei1, ei1 + E1V, Wib, l111b, l211b, a1h, E1V); // k4
    edge_kernel<<<eg(E2V), blk>>>(y0, ei2, ei2 + E2V, Wib, l222b, l211b, a2h, E2V); // k5

    // fused gather-GEMM-scatter aggregation passes (f16 REDs)
    // (1,1,1): a1[t0] += L111(relu(y1[t1]+y1[t2]+b))       <- ncu slot 6
    run_ggemm(y1, y1, t111 + TV, t111 + 2 * TV, t111, Wib, l111W, a1h, TV);
    // (2,2,2): a2[t0] += L222(relu(y2[t1]+y2[t2]+b))
    run_ggemm(y2, y2, t222 + TV, t222 + 2 * TV, t222, Wib, l222W, a2h, TV);
    // (1,1,2) part a: a2[t2] += L211(relu(y1[t0]+y1[t1]+b))
    run_ggemm(y1, y1, t112, t112 + TV, t112 + 2 * TV, Wib, l211W, a2h, TV);
    // (1,1,2) part b: v[t0] += L211(relu(y1[t1]+y2[t2]+b))
    run_ggemm(y1, y2, t112 + TV, t112 + 2 * TV, t112, Wib, l211W, v, TV);

    // fused output MLPs + residual; loaders add X (and v terms on level 1)
    run_fmlp<false, false, false>(a0, x0, m0aW, m0ab, m0bW, m0bb, out,
                                  nullptr, nullptr, nullptr, N0);
    run_fmlp<true, true, true>(a1h, x1, m1aW, m1ab, m1bW, m1bb,
                               out + (size_t)N0 * C, v, inv1, nullptr, E1V);
    run_fmlp<true, true, false>(a2h, x2, m2aW, m2ab, m2bW, m2bb,
                                out + ((size_t)N0 + E1V) * C, nullptr, nullptr, v, E2V);
}